// round 15
// baseline (speedup 1.0000x reference)
#include <cuda_runtime.h>

// Problem constants
#define NB    32
#define NH    64
#define NW    64
#define NT    100
#define COUT  8
#define KS    6
#define LP    2

#define TILE_W 16
#define TILE_H 8
#define HALO_W (TILE_W + KS - 1)   // 21
#define HALO_H (TILE_H + KS - 1)   // 13
#define NPIX   (HALO_W * HALO_H)   // 273
#define KTHR   128                 // one thread per output pixel, all 8 couts
#define NCH    13                  // chunks 0..11: 8 timesteps, chunk 12: 4
#define NHW    (NH * NW)
#define NHWT   (NH * NW * NT)
#define NTILE  32                  // 4 x 8 tiles per image
#define PSTRIDE 6                  // u64 per pixel (48B): 16B-aligned cp16, conflict-free LDS.128

typedef unsigned long long u64;

// chained-recurrence state: u per (b, cout, pixel)  (4 MB)
__device__ float g_u[(size_t)NB * COUT * NHW];
// progress flag per (b, tile): value = number of chunks completed
__device__ int g_flag[NB * NTILE];

__device__ __forceinline__ void upk2(u64 v, float& lo, float& hi) {
    asm("mov.b64 {%0, %1}, %2;" : "=f"(lo), "=f"(hi) : "l"(v));
}
__device__ __forceinline__ u64 fma2(u64 a, u64 b, u64 c) {
    u64 d; asm("fma.rn.f32x2 %0, %1, %2, %3;" : "=l"(d) : "l"(a), "l"(b), "l"(c)); return d;
}
__device__ __forceinline__ unsigned smem_u32(const void* p) {
    return (unsigned)__cvta_generic_to_shared(p);
}
__device__ __forceinline__ void cp16(unsigned dst, const void* src) {
    asm volatile("cp.async.ca.shared.global [%0], [%1], 16;" :: "r"(dst), "l"(src));
}
__device__ __forceinline__ void cp_commit() { asm volatile("cp.async.commit_group;" ::: "memory"); }
__device__ __forceinline__ void cp_wait0()  { asm volatile("cp.async.wait_group 0;" ::: "memory"); }

__device__ __forceinline__ int ld_acq(const int* p) {
    int v; asm volatile("ld.global.acquire.gpu.s32 %0, [%1];" : "=r"(v) : "l"(p) : "memory");
    return v;
}
__device__ __forceinline__ void st_rel(int* p, int v) {
    asm volatile("st.global.release.gpu.s32 [%0], %1;" :: "l"(p), "r"(v) : "memory");
}

// K0: reset progress flags (runs first in every launch/replay)
__global__ void k0_reset() {
    int i = blockIdx.x * blockDim.x + threadIdx.x;
    if (i < NB * NTILE) g_flag[i] = 0;
}

// ============= fused conv + chained recurrence =============
// One block per (w-tile, h-tile, b, chunk); chunk is the slowest dispatch dim.
__global__ __launch_bounds__(KTHR)
void k_fused_chain(const float* __restrict__ x,
                   const float* __restrict__ w,
                   const float* __restrict__ thr_p,
                   float* __restrict__ out)
{
    __shared__ __align__(16) u64 sx[NPIX * PSTRIDE];
    __shared__ __align__(16) u64 sw2[KS * KS * COUT];   // tap-major, (w,w) duplicated

    const int tx    = threadIdx.x;
    const int ty    = threadIdx.y;
    const int tid   = tx + TILE_W * ty;
    const int chunk = blockIdx.z / NB;          // slowest -> dispatch-ordered
    const int b     = blockIdx.z % NB;
    const int t0    = chunk * 8;
    const bool full = (chunk != NCH - 1);
    const int h0    = blockIdx.y * TILE_H;
    const int w0    = blockIdx.x * TILE_W;
    const int tile  = blockIdx.y * 4 + blockIdx.x;

    for (int i = tid; i < KS * KS * COUT; i += KTHR) {
        int tap = i >> 3, c = i & 7;
        unsigned bits = __float_as_uint(w[c * (KS * KS) + tap]);
        sw2[i] = ((u64)bits << 32) | (u64)bits;
    }

    const float* xb = x + (size_t)b * NH * NW * NT;
    const int n16 = full ? 2 : 1;
    for (int idx = tid; idx < NPIX * n16; idx += KTHR) {
        int pix = (n16 == 2) ? (idx >> 1) : idx;
        int j   = (n16 == 2) ? (idx & 1) : 0;
        int r = pix / HALO_W, c = pix % HALO_W;
        int gh = h0 - LP + r, gw = w0 - LP + c;
        if (gh >= 0 && gh < NH && gw >= 0 && gw < NW) {
            const float* src = xb + ((size_t)gh * NW + gw) * NT + t0 + j * 4;
            cp16(smem_u32(&sx[pix * PSTRIDE + j * 2]), src);
        } else {
            sx[pix * PSTRIDE + j * 2 + 0] = 0ull;
            sx[pix * PSTRIDE + j * 2 + 1] = 0ull;
        }
    }
    cp_commit();
    cp_wait0();
    __syncthreads();

    // ---- conv (fully parallel part) ----
    u64 A0[COUT], A1[COUT], A2[COUT], A3[COUT];
#pragma unroll
    for (int c = 0; c < COUT; c++) { A0[c] = 0; A1[c] = 0; A2[c] = 0; A3[c] = 0; }

    if (full) {
#pragma unroll
        for (int kh = 0; kh < KS; kh++) {
#pragma unroll
            for (int kw = 0; kw < KS; kw++) {
                const int tap = kh * KS + kw;
                const u64* xp = &sx[((ty + kh) * HALO_W + (tx + kw)) * PSTRIDE];
                ulonglong2 xA = *(const ulonglong2*)(xp);
                ulonglong2 xB = *(const ulonglong2*)(xp + 2);
                ulonglong2 w01 = *(const ulonglong2*)&sw2[tap * COUT + 0];
                ulonglong2 w23 = *(const ulonglong2*)&sw2[tap * COUT + 2];
                ulonglong2 w45 = *(const ulonglong2*)&sw2[tap * COUT + 4];
                ulonglong2 w67 = *(const ulonglong2*)&sw2[tap * COUT + 6];
                A0[0] = fma2(xA.x, w01.x, A0[0]); A1[0] = fma2(xA.y, w01.x, A1[0]);
                A2[0] = fma2(xB.x, w01.x, A2[0]); A3[0] = fma2(xB.y, w01.x, A3[0]);
                A0[1] = fma2(xA.x, w01.y, A0[1]); A1[1] = fma2(xA.y, w01.y, A1[1]);
                A2[1] = fma2(xB.x, w01.y, A2[1]); A3[1] = fma2(xB.y, w01.y, A3[1]);
                A0[2] = fma2(xA.x, w23.x, A0[2]); A1[2] = fma2(xA.y, w23.x, A1[2]);
                A2[2] = fma2(xB.x, w23.x, A2[2]); A3[2] = fma2(xB.y, w23.x, A3[2]);
                A0[3] = fma2(xA.x, w23.y, A0[3]); A1[3] = fma2(xA.y, w23.y, A1[3]);
                A2[3] = fma2(xB.x, w23.y, A2[3]); A3[3] = fma2(xB.y, w23.y, A3[3]);
                A0[4] = fma2(xA.x, w45.x, A0[4]); A1[4] = fma2(xA.y, w45.x, A1[4]);
                A2[4] = fma2(xB.x, w45.x, A2[4]); A3[4] = fma2(xB.y, w45.x, A3[4]);
                A0[5] = fma2(xA.x, w45.y, A0[5]); A1[5] = fma2(xA.y, w45.y, A1[5]);
                A2[5] = fma2(xB.x, w45.y, A2[5]); A3[5] = fma2(xB.y, w45.y, A3[5]);
                A0[6] = fma2(xA.x, w67.x, A0[6]); A1[6] = fma2(xA.y, w67.x, A1[6]);
                A2[6] = fma2(xB.x, w67.x, A2[6]); A3[6] = fma2(xB.y, w67.x, A3[6]);
                A0[7] = fma2(xA.x, w67.y, A0[7]); A1[7] = fma2(xA.y, w67.y, A1[7]);
                A2[7] = fma2(xB.x, w67.y, A2[7]); A3[7] = fma2(xB.y, w67.y, A3[7]);
            }
        }
    } else {
#pragma unroll
        for (int kh = 0; kh < KS; kh++) {
#pragma unroll
            for (int kw = 0; kw < KS; kw++) {
                const int tap = kh * KS + kw;
                const u64* xp = &sx[((ty + kh) * HALO_W + (tx + kw)) * PSTRIDE];
                ulonglong2 xA = *(const ulonglong2*)(xp);
                ulonglong2 w01 = *(const ulonglong2*)&sw2[tap * COUT + 0];
                ulonglong2 w23 = *(const ulonglong2*)&sw2[tap * COUT + 2];
                ulonglong2 w45 = *(const ulonglong2*)&sw2[tap * COUT + 4];
                ulonglong2 w67 = *(const ulonglong2*)&sw2[tap * COUT + 6];
                A0[0] = fma2(xA.x, w01.x, A0[0]); A1[0] = fma2(xA.y, w01.x, A1[0]);
                A0[1] = fma2(xA.x, w01.y, A0[1]); A1[1] = fma2(xA.y, w01.y, A1[1]);
                A0[2] = fma2(xA.x, w23.x, A0[2]); A1[2] = fma2(xA.y, w23.x, A1[2]);
                A0[3] = fma2(xA.x, w23.y, A0[3]); A1[3] = fma2(xA.y, w23.y, A1[3]);
                A0[4] = fma2(xA.x, w45.x, A0[4]); A1[4] = fma2(xA.y, w45.x, A1[4]);
                A0[5] = fma2(xA.x, w45.y, A0[5]); A1[5] = fma2(xA.y, w45.y, A1[5]);
                A0[6] = fma2(xA.x, w67.x, A0[6]); A1[6] = fma2(xA.y, w67.x, A1[6]);
                A0[7] = fma2(xA.x, w67.y, A0[7]); A1[7] = fma2(xA.y, w67.y, A1[7]);
            }
        }
    }

    // ---- chained recurrence ----
    const int pix = (h0 + ty) * NW + (w0 + tx);
    int* flag = &g_flag[b * NTILE + tile];
    float* ub = g_u + ((size_t)b * COUT) * NHW + pix;
    const float thr = thr_p[0];

    float u[COUT];
    if (chunk == 0) {
#pragma unroll
        for (int c = 0; c < COUT; c++) u[c] = 0.f;
    } else {
        // wait for predecessor chunk of this (b, tile); conv already done above
        while (ld_acq(flag) < chunk) { __nanosleep(64); }
#pragma unroll
        for (int c = 0; c < COUT; c++) u[c] = ub[(size_t)c * NHW];
    }

    float* ob = out + (size_t)b * COUT * NHWT + (size_t)pix * NT + t0;
    const int nt = full ? 8 : 4;
#pragma unroll
    for (int c = 0; c < COUT; c++) {
        float f[8];
        upk2(A0[c], f[0], f[1]); upk2(A1[c], f[2], f[3]);
        upk2(A2[c], f[4], f[5]); upk2(A3[c], f[6], f[7]);
        float uu = u[c];
        float s[8];
#pragma unroll
        for (int tt = 0; tt < 8; tt++) {
            if (tt < nt) {
                // exact reference: ut = (ut - st_prev*thr) + wx ; st = (ut > 0)
                uu = (uu - (uu > 0.f ? thr : 0.f)) + f[tt];
                s[tt] = (uu > 0.f) ? 1.f : 0.f;
            }
        }
        u[c] = uu;
        float* oc = ob + (size_t)c * NHWT;
        __stcs((float4*)oc, make_float4(s[0], s[1], s[2], s[3]));
        if (full) __stcs((float4*)oc + 1, make_float4(s[4], s[5], s[6], s[7]));
    }

    if (chunk < NCH - 1) {
        // publish state for successor chunk
#pragma unroll
        for (int c = 0; c < COUT; c++) ub[(size_t)c * NHW] = u[c];
        __threadfence();        // make this thread's u stores device-visible
        __syncthreads();        // all threads' fenced stores precede the flag
        if (tid == 0) st_rel(flag, chunk + 1);
    }
}

extern "C" void kernel_launch(void* const* d_in, const int* in_sizes, int n_in,
                              void* d_out, int out_size)
{
    const float* x   = (const float*)d_in[0];  // [32,1,64,64,100]
    const float* w   = (const float*)d_in[1];  // [8,1,6,6]
    const float* thr = (const float*)d_in[2];  // [1]
    float* out = (float*)d_out;                // [32,8,64,64,100]

    k0_reset<<<1, NB * NTILE>>>();             // reset chain flags (replay-safe)

    dim3 blk(TILE_W, TILE_H, 1);               // 128 threads
    dim3 grd(NW / TILE_W, NH / TILE_H, NB * NCH);  // (4, 8, 416); chunk slowest
    k_fused_chain<<<grd, blk>>>(x, w, thr, out);
}

// round 16
// speedup vs baseline: 1.7643x; 1.7643x over previous
#include <cuda_runtime.h>

// Problem constants
#define NB    32
#define NH    64
#define NW    64
#define NT    100
#define COUT  8
#define KS    6
#define LP    2

#define TILE_W 16
#define TILE_H 8
#define HALO_W (TILE_W + KS - 1)   // 21
#define HALO_H (TILE_H + KS - 1)   // 13
#define NPIX   (HALO_W * HALO_H)   // 273
#define KTHR   128                 // one thread per output pixel, all 8 couts
#define NCHF   12                  // full chunks of 8 t; tail chunk of 4 (t=96..99)
#define NHW    (NH * NW)
#define NHWT   (NH * NW * NT)
#define PSTRIDE 51                 // u64 per pixel (50 data + 1 pad = 408B):
                                   // 8B-aligned cp8/LDS.64; bank step 6 -> <=2-way
                                   // conflict = free for LDS.64 (2 natural wavefronts)
#define SX_U64  (NPIX * PSTRIDE + 1)          // 13924 (padded even -> sw2 16B aligned)
#define SW_U64  (KS * KS * COUT)              // 288
#define SMEM_U64 (SX_U64 + SW_U64)            // 14212
#define SMEM_BYTES (SMEM_U64 * 8)             // 113696 -> 2 blocks/SM

typedef unsigned long long u64;

__device__ __forceinline__ void upk2(u64 v, float& lo, float& hi) {
    asm("mov.b64 {%0, %1}, %2;" : "=f"(lo), "=f"(hi) : "l"(v));
}
__device__ __forceinline__ u64 fma2(u64 a, u64 b, u64 c) {
    u64 d; asm("fma.rn.f32x2 %0, %1, %2, %3;" : "=l"(d) : "l"(a), "l"(b), "l"(c)); return d;
}
__device__ __forceinline__ unsigned smem_u32(const void* p) {
    return (unsigned)__cvta_generic_to_shared(p);
}
__device__ __forceinline__ void cp8(unsigned dst, const void* src) {
    asm volatile("cp.async.ca.shared.global [%0], [%1], 8;" :: "r"(dst), "l"(src));
}
__device__ __forceinline__ void cp_commit() { asm volatile("cp.async.commit_group;" ::: "memory"); }
__device__ __forceinline__ void cp_wait0()  { asm volatile("cp.async.wait_group 0;" ::: "memory"); }

__global__ __launch_bounds__(KTHR)
void k_allt(const float* __restrict__ x,
            const float* __restrict__ w,
            const float* __restrict__ thr_p,
            float* __restrict__ out)
{
    extern __shared__ __align__(16) u64 smem[];
    u64* sx  = smem;                 // [NPIX][PSTRIDE] : all 100 timesteps resident
    u64* sw2 = smem + SX_U64;        // tap-major weights, (w,w) duplicated

    const int tx  = threadIdx.x;
    const int ty  = threadIdx.y;
    const int tid = tx + TILE_W * ty;
    const int b   = blockIdx.z;
    const int h0  = blockIdx.y * TILE_H;
    const int w0  = blockIdx.x * TILE_W;

    // weights: transpose [cout][tap] -> [tap][cout], duplicate into f32x2 lanes
    for (int i = tid; i < SW_U64; i += KTHR) {
        int tap = i >> 3, c = i & 7;
        unsigned bits = __float_as_uint(w[c * (KS * KS) + tap]);
        sw2[i] = ((u64)bits << 32) | (u64)bits;
    }

    // ---- load the ENTIRE halo x tile (all 100 t) once: 50 cp8 per pixel ----
    const float* xb = x + (size_t)b * NHW * NT;
    for (int idx = tid; idx < NPIX * 50; idx += KTHR) {
        int pix = idx / 50;
        int j   = idx - pix * 50;          // u64 index within pixel (2 timesteps)
        int r = pix / HALO_W, c = pix - r * HALO_W;
        int gh = h0 - LP + r, gw = w0 - LP + c;
        if (gh >= 0 && gh < NH && gw >= 0 && gw < NW) {
            cp8(smem_u32(&sx[pix * PSTRIDE + j]),
                xb + ((size_t)gh * NW + gw) * NT + j * 2);
        } else {
            sx[pix * PSTRIDE + j] = 0ull;
        }
    }
    cp_commit();
    cp_wait0();
    __syncthreads();     // the ONLY barrier in the kernel

    const float thr = thr_p[0];
    const int pix = (h0 + ty) * NW + (w0 + tx);
    float* ob = out + (size_t)b * COUT * NHWT + (size_t)pix * NT;
    const u64* sb = &sx[(ty * HALO_W + tx) * PSTRIDE];

    float ut[COUT];
#pragma unroll
    for (int c = 0; c < COUT; c++) ut[c] = 0.f;

    // ---- 12 full chunks, NO barriers, NO loads from global ----
#pragma unroll 1
    for (int ch = 0; ch < NCHF; ch++) {
        const u64* base = sb + ch * 4;

        u64 a0[COUT], a1[COUT], a2[COUT], a3[COUT];
#pragma unroll
        for (int c = 0; c < COUT; c++) { a0[c] = 0; a1[c] = 0; a2[c] = 0; a3[c] = 0; }

        // flat tap loop with one-tap x prefetch (R8 pattern), LDS.64 x-loads
        u64 x0 = base[0], x1 = base[1], x2 = base[2], x3 = base[3];
#pragma unroll
        for (int tap = 0; tap < KS * KS; tap++) {
            u64 n0, n1, n2, n3;
            if (tap + 1 < KS * KS) {
                const int nkh = (tap + 1) / KS, nkw = (tap + 1) - nkh * KS;
                const u64* np = base + (nkh * HALO_W + nkw) * PSTRIDE;
                n0 = np[0]; n1 = np[1]; n2 = np[2]; n3 = np[3];
            }
            ulonglong2 w01 = *(const ulonglong2*)&sw2[tap * COUT + 0];
            ulonglong2 w23 = *(const ulonglong2*)&sw2[tap * COUT + 2];
            ulonglong2 w45 = *(const ulonglong2*)&sw2[tap * COUT + 4];
            ulonglong2 w67 = *(const ulonglong2*)&sw2[tap * COUT + 6];
            a0[0] = fma2(x0, w01.x, a0[0]); a1[0] = fma2(x1, w01.x, a1[0]);
            a2[0] = fma2(x2, w01.x, a2[0]); a3[0] = fma2(x3, w01.x, a3[0]);
            a0[1] = fma2(x0, w01.y, a0[1]); a1[1] = fma2(x1, w01.y, a1[1]);
            a2[1] = fma2(x2, w01.y, a2[1]); a3[1] = fma2(x3, w01.y, a3[1]);
            a0[2] = fma2(x0, w23.x, a0[2]); a1[2] = fma2(x1, w23.x, a1[2]);
            a2[2] = fma2(x2, w23.x, a2[2]); a3[2] = fma2(x3, w23.x, a3[2]);
            a0[3] = fma2(x0, w23.y, a0[3]); a1[3] = fma2(x1, w23.y, a1[3]);
            a2[3] = fma2(x2, w23.y, a2[3]); a3[3] = fma2(x3, w23.y, a3[3]);
            a0[4] = fma2(x0, w45.x, a0[4]); a1[4] = fma2(x1, w45.x, a1[4]);
            a2[4] = fma2(x2, w45.x, a2[4]); a3[4] = fma2(x3, w45.x, a3[4]);
            a0[5] = fma2(x0, w45.y, a0[5]); a1[5] = fma2(x1, w45.y, a1[5]);
            a2[5] = fma2(x2, w45.y, a2[5]); a3[5] = fma2(x3, w45.y, a3[5]);
            a0[6] = fma2(x0, w67.x, a0[6]); a1[6] = fma2(x1, w67.x, a1[6]);
            a2[6] = fma2(x2, w67.x, a2[6]); a3[6] = fma2(x3, w67.x, a3[6]);
            a0[7] = fma2(x0, w67.y, a0[7]); a1[7] = fma2(x1, w67.y, a1[7]);
            a2[7] = fma2(x2, w67.y, a2[7]); a3[7] = fma2(x3, w67.y, a3[7]);
            if (tap + 1 < KS * KS) { x0 = n0; x1 = n1; x2 = n2; x3 = n3; }
        }

        // recurrence + stores (exact reference order)
        const int t0 = ch * 8;
#pragma unroll
        for (int c = 0; c < COUT; c++) {
            float f0, f1, f2, f3, f4, f5, f6, f7;
            upk2(a0[c], f0, f1); upk2(a1[c], f2, f3);
            upk2(a2[c], f4, f5); upk2(a3[c], f6, f7);
            float u = ut[c];
            float s0, s1, s2, s3, s4, s5, s6, s7;
            u = (u - (u > 0.f ? thr : 0.f)) + f0; s0 = (u > 0.f) ? 1.f : 0.f;
            u = (u - (u > 0.f ? thr : 0.f)) + f1; s1 = (u > 0.f) ? 1.f : 0.f;
            u = (u - (u > 0.f ? thr : 0.f)) + f2; s2 = (u > 0.f) ? 1.f : 0.f;
            u = (u - (u > 0.f ? thr : 0.f)) + f3; s3 = (u > 0.f) ? 1.f : 0.f;
            u = (u - (u > 0.f ? thr : 0.f)) + f4; s4 = (u > 0.f) ? 1.f : 0.f;
            u = (u - (u > 0.f ? thr : 0.f)) + f5; s5 = (u > 0.f) ? 1.f : 0.f;
            u = (u - (u > 0.f ? thr : 0.f)) + f6; s6 = (u > 0.f) ? 1.f : 0.f;
            u = (u - (u > 0.f ? thr : 0.f)) + f7; s7 = (u > 0.f) ? 1.f : 0.f;
            ut[c] = u;
            float* oc = ob + (size_t)c * NHWT + t0;
            __stcs((float4*)oc,     make_float4(s0, s1, s2, s3));
            __stcs((float4*)oc + 1, make_float4(s4, s5, s6, s7));
        }
    }

    // ---- tail chunk: t = 96..99 ----
    {
        const u64* base = sb + NCHF * 4;    // u64 48, 49
        u64 a0[COUT], a1[COUT];
#pragma unroll
        for (int c = 0; c < COUT; c++) { a0[c] = 0; a1[c] = 0; }
#pragma unroll
        for (int kh = 0; kh < KS; kh++) {
#pragma unroll
            for (int kw = 0; kw < KS; kw++) {
                const int tap = kh * KS + kw;
                const u64* xp = base + (kh * HALO_W + kw) * PSTRIDE;
                u64 x0 = xp[0], x1 = xp[1];
                ulonglong2 w01 = *(const ulonglong2*)&sw2[tap * COUT + 0];
                ulonglong2 w23 = *(const ulonglong2*)&sw2[tap * COUT + 2];
                ulonglong2 w45 = *(const ulonglong2*)&sw2[tap * COUT + 4];
                ulonglong2 w67 = *(const ulonglong2*)&sw2[tap * COUT + 6];
                a0[0] = fma2(x0, w01.x, a0[0]); a1[0] = fma2(x1, w01.x, a1[0]);
                a0[1] = fma2(x0, w01.y, a0[1]); a1[1] = fma2(x1, w01.y, a1[1]);
                a0[2] = fma2(x0, w23.x, a0[2]); a1[2] = fma2(x1, w23.x, a1[2]);
                a0[3] = fma2(x0, w23.y, a0[3]); a1[3] = fma2(x1, w23.y, a1[3]);
                a0[4] = fma2(x0, w45.x, a0[4]); a1[4] = fma2(x1, w45.x, a1[4]);
                a0[5] = fma2(x0, w45.y, a0[5]); a1[5] = fma2(x1, w45.y, a1[5]);
                a0[6] = fma2(x0, w67.x, a0[6]); a1[6] = fma2(x1, w67.x, a1[6]);
                a0[7] = fma2(x0, w67.y, a0[7]); a1[7] = fma2(x1, w67.y, a1[7]);
            }
        }
#pragma unroll
        for (int c = 0; c < COUT; c++) {
            float f0, f1, f2, f3;
            upk2(a0[c], f0, f1); upk2(a1[c], f2, f3);
            float u = ut[c];
            float s0, s1, s2, s3;
            u = (u - (u > 0.f ? thr : 0.f)) + f0; s0 = (u > 0.f) ? 1.f : 0.f;
            u = (u - (u > 0.f ? thr : 0.f)) + f1; s1 = (u > 0.f) ? 1.f : 0.f;
            u = (u - (u > 0.f ? thr : 0.f)) + f2; s2 = (u > 0.f) ? 1.f : 0.f;
            u = (u - (u > 0.f ? thr : 0.f)) + f3; s3 = (u > 0.f) ? 1.f : 0.f;
            __stcs((float4*)(ob + (size_t)c * NHWT + 96), make_float4(s0, s1, s2, s3));
        }
    }
}

extern "C" void kernel_launch(void* const* d_in, const int* in_sizes, int n_in,
                              void* d_out, int out_size)
{
    const float* x   = (const float*)d_in[0];  // [32,1,64,64,100]
    const float* w   = (const float*)d_in[1];  // [8,1,6,6]
    const float* thr = (const float*)d_in[2];  // [1]
    float* out = (float*)d_out;                // [32,8,64,64,100]

    cudaFuncSetAttribute(k_allt, cudaFuncAttributeMaxDynamicSharedMemorySize,
                         SMEM_BYTES);

    dim3 blk(TILE_W, TILE_H, 1);               // 128 threads
    dim3 grd(NW / TILE_W, NH / TILE_H, NB);    // (4, 8, 32) = 1024 blocks
    k_allt<<<grd, blk, SMEM_BYTES>>>(x, w, thr, out);
}

// round 17
// speedup vs baseline: 1.8001x; 1.0203x over previous
#include <cuda_runtime.h>

// Problem constants
#define NB    32
#define NH    64
#define NW    64
#define NT    100
#define COUT  8
#define KS    6
#define LP    2

#define TILE_W 16
#define TILE_H 8
#define HALO_W (TILE_W + KS - 1)   // 21
#define HALO_H (TILE_H + KS - 1)   // 13
#define NPIX   (HALO_W * HALO_H)   // 273
#define KTHR   256                 // 16 x 8 x 2: pixel x cout-half
#define CPT    4                   // couts per thread
#define NCHF   12                  // full chunks of 8 t; tail chunk of 4 (t=96..99)
#define NHW    (NH * NW)
#define NHWT   (NH * NW * NT)
#define PSTRIDE 51                 // u64 per pixel (50 data + 1 pad = 408B), 8B-aligned
#define SX_U64  (NPIX * PSTRIDE + 1)          // 13924
#define SW_U64  (KS * KS * COUT)              // 288
#define SMEM_U64 (SX_U64 + SW_U64)            // 14212
#define SMEM_BYTES (SMEM_U64 * 8)             // 113696 -> 2 blocks/SM, 16 warps/SM

typedef unsigned long long u64;

__device__ __forceinline__ void upk2(u64 v, float& lo, float& hi) {
    asm("mov.b64 {%0, %1}, %2;" : "=f"(lo), "=f"(hi) : "l"(v));
}
__device__ __forceinline__ u64 fma2(u64 a, u64 b, u64 c) {
    u64 d; asm("fma.rn.f32x2 %0, %1, %2, %3;" : "=l"(d) : "l"(a), "l"(b), "l"(c)); return d;
}
__device__ __forceinline__ unsigned smem_u32(const void* p) {
    return (unsigned)__cvta_generic_to_shared(p);
}
__device__ __forceinline__ void cp8(unsigned dst, const void* src) {
    asm volatile("cp.async.ca.shared.global [%0], [%1], 8;" :: "r"(dst), "l"(src));
}
__device__ __forceinline__ void cp_commit() { asm volatile("cp.async.commit_group;" ::: "memory"); }
__device__ __forceinline__ void cp_wait0()  { asm volatile("cp.async.wait_group 0;" ::: "memory"); }

__global__ __launch_bounds__(KTHR, 2)
void k_allt(const float* __restrict__ x,
            const float* __restrict__ w,
            const float* __restrict__ thr_p,
            float* __restrict__ out)
{
    extern __shared__ __align__(16) u64 smem[];
    u64* sx  = smem;                 // [NPIX][PSTRIDE] : all 100 timesteps resident
    u64* sw2 = smem + SX_U64;        // tap-major weights, (w,w) duplicated

    const int tx  = threadIdx.x;
    const int ty  = threadIdx.y;
    const int cz  = threadIdx.z;                       // cout half
    const int tid = tx + TILE_W * ty + (TILE_W * TILE_H) * cz;
    const int b   = blockIdx.z;
    const int h0  = blockIdx.y * TILE_H;
    const int w0  = blockIdx.x * TILE_W;

    // weights: transpose [cout][tap] -> [tap][cout], duplicate into f32x2 lanes
    for (int i = tid; i < SW_U64; i += KTHR) {
        int tap = i >> 3, c = i & 7;
        unsigned bits = __float_as_uint(w[c * (KS * KS) + tap]);
        sw2[i] = ((u64)bits << 32) | (u64)bits;
    }

    // ---- load the ENTIRE halo x tile (all 100 t) once: 50 cp8 per pixel ----
    const float* xb = x + (size_t)b * NHW * NT;
    for (int idx = tid; idx < NPIX * 50; idx += KTHR) {
        int pix = idx / 50;
        int j   = idx - pix * 50;          // u64 index within pixel (2 timesteps)
        int r = pix / HALO_W, c = pix - r * HALO_W;
        int gh = h0 - LP + r, gw = w0 - LP + c;
        if (gh >= 0 && gh < NH && gw >= 0 && gw < NW) {
            cp8(smem_u32(&sx[pix * PSTRIDE + j]),
                xb + ((size_t)gh * NW + gw) * NT + j * 2);
        } else {
            sx[pix * PSTRIDE + j] = 0ull;
        }
    }
    cp_commit();
    cp_wait0();
    __syncthreads();     // the ONLY barrier in the kernel

    const float thr = thr_p[0];
    const int pix = (h0 + ty) * NW + (w0 + tx);
    const int cbase = cz * CPT;
    float* ob = out + (size_t)b * COUT * NHWT + (size_t)pix * NT
                    + (size_t)cbase * NHWT;
    const u64* sb = &sx[(ty * HALO_W + tx) * PSTRIDE];

    float ut[CPT];
#pragma unroll
    for (int c = 0; c < CPT; c++) ut[c] = 0.f;

    // ---- 12 full chunks, NO barriers, NO global loads ----
#pragma unroll 1
    for (int ch = 0; ch < NCHF; ch++) {
        const u64* base = sb + ch * 4;

        u64 a0[CPT], a1[CPT], a2[CPT], a3[CPT];
#pragma unroll
        for (int c = 0; c < CPT; c++) { a0[c] = 0; a1[c] = 0; a2[c] = 0; a3[c] = 0; }

        // flat tap loop with one-tap x prefetch
        u64 x0 = base[0], x1 = base[1], x2 = base[2], x3 = base[3];
#pragma unroll
        for (int tap = 0; tap < KS * KS; tap++) {
            u64 n0, n1, n2, n3;
            if (tap + 1 < KS * KS) {
                const int nkh = (tap + 1) / KS, nkw = (tap + 1) - nkh * KS;
                const u64* np = base + (nkh * HALO_W + nkw) * PSTRIDE;
                n0 = np[0]; n1 = np[1]; n2 = np[2]; n3 = np[3];
            }
            ulonglong2 wA = *(const ulonglong2*)&sw2[tap * COUT + cbase];
            ulonglong2 wB = *(const ulonglong2*)&sw2[tap * COUT + cbase + 2];
            a0[0] = fma2(x0, wA.x, a0[0]); a1[0] = fma2(x1, wA.x, a1[0]);
            a2[0] = fma2(x2, wA.x, a2[0]); a3[0] = fma2(x3, wA.x, a3[0]);
            a0[1] = fma2(x0, wA.y, a0[1]); a1[1] = fma2(x1, wA.y, a1[1]);
            a2[1] = fma2(x2, wA.y, a2[1]); a3[1] = fma2(x3, wA.y, a3[1]);
            a0[2] = fma2(x0, wB.x, a0[2]); a1[2] = fma2(x1, wB.x, a1[2]);
            a2[2] = fma2(x2, wB.x, a2[2]); a3[2] = fma2(x3, wB.x, a3[2]);
            a0[3] = fma2(x0, wB.y, a0[3]); a1[3] = fma2(x1, wB.y, a1[3]);
            a2[3] = fma2(x2, wB.y, a2[3]); a3[3] = fma2(x3, wB.y, a3[3]);
            if (tap + 1 < KS * KS) { x0 = n0; x1 = n1; x2 = n2; x3 = n3; }
        }

        // recurrence + stores (exact reference order)
        const int t0 = ch * 8;
#pragma unroll
        for (int c = 0; c < CPT; c++) {
            float f0, f1, f2, f3, f4, f5, f6, f7;
            upk2(a0[c], f0, f1); upk2(a1[c], f2, f3);
            upk2(a2[c], f4, f5); upk2(a3[c], f6, f7);
            float u = ut[c];
            float s0, s1, s2, s3, s4, s5, s6, s7;
            u = (u - (u > 0.f ? thr : 0.f)) + f0; s0 = (u > 0.f) ? 1.f : 0.f;
            u = (u - (u > 0.f ? thr : 0.f)) + f1; s1 = (u > 0.f) ? 1.f : 0.f;
            u = (u - (u > 0.f ? thr : 0.f)) + f2; s2 = (u > 0.f) ? 1.f : 0.f;
            u = (u - (u > 0.f ? thr : 0.f)) + f3; s3 = (u > 0.f) ? 1.f : 0.f;
            u = (u - (u > 0.f ? thr : 0.f)) + f4; s4 = (u > 0.f) ? 1.f : 0.f;
            u = (u - (u > 0.f ? thr : 0.f)) + f5; s5 = (u > 0.f) ? 1.f : 0.f;
            u = (u - (u > 0.f ? thr : 0.f)) + f6; s6 = (u > 0.f) ? 1.f : 0.f;
            u = (u - (u > 0.f ? thr : 0.f)) + f7; s7 = (u > 0.f) ? 1.f : 0.f;
            ut[c] = u;
            float* oc = ob + (size_t)c * NHWT + t0;
            __stcs((float4*)oc,     make_float4(s0, s1, s2, s3));
            __stcs((float4*)oc + 1, make_float4(s4, s5, s6, s7));
        }
    }

    // ---- tail chunk: t = 96..99 ----
    {
        const u64* base = sb + NCHF * 4;    // u64 48, 49
        u64 a0[CPT], a1[CPT];
#pragma unroll
        for (int c = 0; c < CPT; c++) { a0[c] = 0; a1[c] = 0; }
#pragma unroll
        for (int kh = 0; kh < KS; kh++) {
#pragma unroll
            for (int kw = 0; kw < KS; kw++) {
                const int tap = kh * KS + kw;
                const u64* xp = base + (kh * HALO_W + kw) * PSTRIDE;
                u64 x0 = xp[0], x1 = xp[1];
                ulonglong2 wA = *(const ulonglong2*)&sw2[tap * COUT + cbase];
                ulonglong2 wB = *(const ulonglong2*)&sw2[tap * COUT + cbase + 2];
                a0[0] = fma2(x0, wA.x, a0[0]); a1[0] = fma2(x1, wA.x, a1[0]);
                a0[1] = fma2(x0, wA.y, a0[1]); a1[1] = fma2(x1, wA.y, a1[1]);
                a0[2] = fma2(x0, wB.x, a0[2]); a1[2] = fma2(x1, wB.x, a1[2]);
                a0[3] = fma2(x0, wB.y, a0[3]); a1[3] = fma2(x1, wB.y, a1[3]);
            }
        }
#pragma unroll
        for (int c = 0; c < CPT; c++) {
            float f0, f1, f2, f3;
            upk2(a0[c], f0, f1); upk2(a1[c], f2, f3);
            float u = ut[c];
            float s0, s1, s2, s3;
            u = (u - (u > 0.f ? thr : 0.f)) + f0; s0 = (u > 0.f) ? 1.f : 0.f;
            u = (u - (u > 0.f ? thr : 0.f)) + f1; s1 = (u > 0.f) ? 1.f : 0.f;
            u = (u - (u > 0.f ? thr : 0.f)) + f2; s2 = (u > 0.f) ? 1.f : 0.f;
            u = (u - (u > 0.f ? thr : 0.f)) + f3; s3 = (u > 0.f) ? 1.f : 0.f;
            __stcs((float4*)(ob + (size_t)c * NHWT + 96), make_float4(s0, s1, s2, s3));
        }
    }
}

extern "C" void kernel_launch(void* const* d_in, const int* in_sizes, int n_in,
                              void* d_out, int out_size)
{
    const float* x   = (const float*)d_in[0];  // [32,1,64,64,100]
    const float* w   = (const float*)d_in[1];  // [8,1,6,6]
    const float* thr = (const float*)d_in[2];  // [1]
    float* out = (float*)d_out;                // [32,8,64,64,100]

    cudaFuncSetAttribute(k_allt, cudaFuncAttributeMaxDynamicSharedMemorySize,
                         SMEM_BYTES);

    dim3 blk(TILE_W, TILE_H, 2);               // 256 threads
    dim3 grd(NW / TILE_W, NH / TILE_H, NB);    // (4, 8, 32) = 1024 blocks
    k_allt<<<grd, blk, SMEM_BYTES>>>(x, w, thr, out);
}